// round 7
// baseline (speedup 1.0000x reference)
#include <cuda_runtime.h>
#include <cuda_bf16.h>

// Problem constants (fixed by reference setup_inputs)
#define BATCH 16
#define CIN   128
#define COUT  128
#define HH    128
#define WW    128
#define SS    512
#define KK    3
#define EPS   1e-8f

typedef unsigned long long u64;

// --- packed f32x2 helpers (Blackwell) --------------------------------------
__device__ __forceinline__ u64 pack2(float lo, float hi) {
    u64 r; asm("mov.b64 %0, {%1,%2};" : "=l"(r) : "f"(lo), "f"(hi)); return r;
}
__device__ __forceinline__ void unpack2(u64 v, float& lo, float& hi) {
    asm("mov.b64 {%0,%1}, %2;" : "=f"(lo), "=f"(hi) : "l"(v));
}
__device__ __forceinline__ void fma2(u64& d, u64 a, u64 b) {
    asm("fma.rn.f32x2 %0, %1, %2, %0;" : "+l"(d) : "l"(a), "l"(b));
}

// Scratch (allocation-free: __device__ globals)
__device__ float g_s[BATCH * CIN];        // modulation scale per (b, ci)
__device__ float g_wsq[COUT * CIN];       // sum_k weight^2 per (co, ci)
__device__ float g_decoef[BATCH * COUT];  // demodulation per (b, co)

// ---------------------------------------------------------------------------
__global__ void k_modscale(const float* __restrict__ style,
                           const float* __restrict__ mod_w,
                           const float* __restrict__ mod_b) {
    int t = blockIdx.x * blockDim.x + threadIdx.x;
    if (t >= BATCH * CIN) return;
    int b = t >> 7;
    int ci = t & 127;
    const float* st = style + b * SS;
    const float* mw = mod_w + ci * SS;
    float acc = 0.f;
#pragma unroll 8
    for (int j = 0; j < SS; ++j) acc = fmaf(st[j], mw[j], acc);
    g_s[t] = acc + mod_b[ci];
}

__global__ void k_wsq(const float* __restrict__ weight) {
    int t = blockIdx.x * blockDim.x + threadIdx.x;
    if (t >= COUT * CIN) return;
    const float* w = weight + t * (KK * KK);
    float acc = 0.f;
#pragma unroll
    for (int k = 0; k < KK * KK; ++k) acc = fmaf(w[k], w[k], acc);
    g_wsq[t] = acc;
}

__global__ void k_decoef() {
    int t = blockIdx.x * blockDim.x + threadIdx.x;
    if (t >= BATCH * COUT) return;
    int b = t >> 7;
    int co = t & 127;
    const float* sv = g_s + b * CIN;
    const float* wq = g_wsq + co * CIN;
    float acc = 0.f;
#pragma unroll 8
    for (int ci = 0; ci < CIN; ++ci) {
        float s = sv[ci];
        acc = fmaf(wq[ci], s * s, acc);
    }
    g_decoef[t] = rsqrtf(acc + EPS);
}

// ---------------------------------------------------------------------------
// Main conv kernel: packed f32x2 FFMA version.
// CTA: one batch b, 32 output channels, 16x16 spatial tile. 256 threads.
// Thread: 4 co x 8 px (4 f32x2 accumulator pairs per co).
#define CO_T   32
#define TILE   16
#define CI_T   8
#define XPITCH 20           // row pitch in floats for x tile (18 used)

__global__ __launch_bounds__(256, 2)
void k_conv(const float* __restrict__ x,
            const float* __restrict__ weight,
            float* __restrict__ out) {
    __shared__ __align__(16) float xs[CI_T][18 * XPITCH];     // scaled input + halo
    __shared__ __align__(16) float ws2[CO_T * CI_T * 9 * 2];  // weights, DUPLICATED (w,w)

    const int tid = threadIdx.x;
    const int b  = blockIdx.z;
    const int co_base = blockIdx.y * CO_T;
    const int h0 = (blockIdx.x >> 3) * TILE;
    const int w0 = (blockIdx.x & 7) * TILE;

    const int co_grp = tid >> 5;        // 0..7
    const int px = tid & 31;
    const int r  = px >> 1;             // output row within tile 0..15
    const int c8 = (px & 1) * 8;        // output col segment base (0 or 8)

    u64 acc2[4][4];                      // [c4][pair]  pair p covers px {2p, 2p+1}
#pragma unroll
    for (int i = 0; i < 4; ++i)
#pragma unroll
        for (int p = 0; p < 4; ++p) acc2[i][p] = 0ull;

    for (int c0 = 0; c0 < CIN; c0 += CI_T) {
        // ---- stage x tile (scaled by s) ----
        for (int i = tid; i < CI_T * 18 * 18; i += 256) {
            int ci = i / 324;
            int rem = i - ci * 324;
            int y = rem / 18;
            int xx = rem - y * 18;
            int gy = h0 - 1 + y;
            int gx = w0 - 1 + xx;
            float v = 0.f;
            if (gy >= 0 && gy < HH && gx >= 0 && gx < WW)
                v = x[(((size_t)b * CIN + c0 + ci) * HH + gy) * WW + gx];
            xs[ci][y * XPITCH + xx] = v * g_s[b * CIN + c0 + ci];
        }
        // ---- stage weights chunk, duplicated for f32x2 broadcast ----
        {
            float2* wv2 = reinterpret_cast<float2*>(ws2);
            for (int i = tid; i < CO_T * CI_T * 9; i += 256) {
                int co_l = i / (CI_T * 9);
                int rem  = i - co_l * (CI_T * 9);
                float w = weight[((co_base + co_l) * CIN + c0) * 9 + rem];
                wv2[i] = make_float2(w, w);
            }
        }
        __syncthreads();

        // ---- compute ----
#pragma unroll 4
        for (int ci = 0; ci < CI_T; ++ci) {
#pragma unroll
            for (int kh = 0; kh < 3; ++kh) {
                // x row segment: 10 floats = 5 LDS.64 + 4 odd-shift packs
                const float2* xrow2 = reinterpret_cast<const float2*>(
                    &xs[ci][(r + kh) * XPITCH + c8]);
                float2 e0 = xrow2[0], e1 = xrow2[1], e2 = xrow2[2],
                       e3 = xrow2[3], e4 = xrow2[4];
                u64 P[9];
                P[0] = pack2(e0.x, e0.y);
                P[2] = pack2(e1.x, e1.y);
                P[4] = pack2(e2.x, e2.y);
                P[6] = pack2(e3.x, e3.y);
                P[8] = pack2(e4.x, e4.y);
                P[1] = pack2(e0.y, e1.x);
                P[3] = pack2(e1.y, e2.x);
                P[5] = pack2(e2.y, e3.x);
                P[7] = pack2(e3.y, e4.x);

                // duplicated weights: one LDS.64 each, warp-uniform broadcast
                const u64* wrow = reinterpret_cast<const u64*>(
                    ws2 + ((co_grp * 4) * (CI_T * 9) + ci * 9 + kh * 3) * 2);
#pragma unroll
                for (int c4 = 0; c4 < 4; ++c4) {
                    u64 w0v = wrow[c4 * (CI_T * 9)];
                    u64 w1v = wrow[c4 * (CI_T * 9) + 1];
                    u64 w2v = wrow[c4 * (CI_T * 9) + 2];
#pragma unroll
                    for (int p = 0; p < 4; ++p) {
                        fma2(acc2[c4][p], w0v, P[2 * p + 0]);
                        fma2(acc2[c4][p], w1v, P[2 * p + 1]);
                        fma2(acc2[c4][p], w2v, P[2 * p + 2]);
                    }
                }
            }
        }
        __syncthreads();
    }

    // ---- store with demodulation (2x STG.128 per c4) ----
#pragma unroll
    for (int c4 = 0; c4 < 4; ++c4) {
        int co = co_base + co_grp * 4 + c4;
        float dc = g_decoef[b * COUT + co];
        float f[8];
#pragma unroll
        for (int p = 0; p < 4; ++p) unpack2(acc2[c4][p], f[2 * p], f[2 * p + 1]);
        float4* op = reinterpret_cast<float4*>(
            out + (((size_t)b * COUT + co) * HH + (h0 + r)) * WW + w0 + c8);
        op[0] = make_float4(f[0] * dc, f[1] * dc, f[2] * dc, f[3] * dc);
        op[1] = make_float4(f[4] * dc, f[5] * dc, f[6] * dc, f[7] * dc);
    }
}

// ---------------------------------------------------------------------------
extern "C" void kernel_launch(void* const* d_in, const int* in_sizes, int n_in,
                              void* d_out, int out_size) {
    const float* x      = (const float*)d_in[0];
    const float* style  = (const float*)d_in[1];
    const float* weight = (const float*)d_in[2];
    const float* mod_w  = (const float*)d_in[3];
    const float* mod_b  = (const float*)d_in[4];
    float* out = (float*)d_out;

    k_modscale<<<(BATCH * CIN + 255) / 256, 256>>>(style, mod_w, mod_b);
    k_wsq<<<(COUT * CIN + 255) / 256, 256>>>(weight);
    k_decoef<<<(BATCH * COUT + 255) / 256, 256>>>();

    dim3 grid((HH / TILE) * (WW / TILE), COUT / CO_T, BATCH);
    k_conv<<<grid, 256>>>(x, weight, out);
}

// round 8
// speedup vs baseline: 1.1558x; 1.1558x over previous
#include <cuda_runtime.h>
#include <cuda_bf16.h>
#include <cstdint>

// Problem constants (fixed by reference setup_inputs)
#define BATCH 16
#define CIN   128
#define COUT  128
#define HH    128
#define WW    128
#define SS    512
#define EPS   1e-8f

// Scratch (allocation-free: __device__ globals)
__device__ float g_s[BATCH * CIN];                    // modulation per (b, ci)
__device__ float g_wsq[COUT * CIN];                   // sum_k weight^2 per (co, ci)
__device__ float g_decoef[BATCH * COUT];              // demod per (b, co)
// fully modulated weights, conv-friendly layout [b][ci][kh][co][kw]
__device__ float g_wmod[BATCH * CIN * 3 * COUT * 3];  // 9.44 MB

// ---------------------------------------------------------------------------
__device__ __forceinline__ uint32_t smem_u32(const void* p) {
    return (uint32_t)__cvta_generic_to_shared(p);
}
__device__ __forceinline__ void cp16(uint32_t dst, const void* src, int sbytes) {
    // 16B async copy; sbytes==0 -> full zero-fill
    asm volatile("cp.async.cg.shared.global [%0], [%1], 16, %2;"
                 :: "r"(dst), "l"(src), "r"(sbytes) : "memory");
}

// ---------------------------------------------------------------------------
__global__ void k_modscale(const float* __restrict__ style,
                           const float* __restrict__ mod_w,
                           const float* __restrict__ mod_b) {
    int t = blockIdx.x * blockDim.x + threadIdx.x;
    if (t >= BATCH * CIN) return;
    int b = t >> 7, ci = t & 127;
    const float* st = style + b * SS;
    const float* mw = mod_w + ci * SS;
    float acc = 0.f;
#pragma unroll 8
    for (int j = 0; j < SS; ++j) acc = fmaf(st[j], mw[j], acc);
    g_s[t] = acc + mod_b[ci];
}

__global__ void k_wsq(const float* __restrict__ weight) {
    int t = blockIdx.x * blockDim.x + threadIdx.x;
    if (t >= COUT * CIN) return;
    const float* w = weight + t * 9;
    float acc = 0.f;
#pragma unroll
    for (int k = 0; k < 9; ++k) acc = fmaf(w[k], w[k], acc);
    g_wsq[t] = acc;
}

__global__ void k_decoef() {
    int t = blockIdx.x * blockDim.x + threadIdx.x;
    if (t >= BATCH * COUT) return;
    int b = t >> 7, co = t & 127;
    const float* sv = g_s + b * CIN;
    const float* wq = g_wsq + co * CIN;
    float acc = 0.f;
#pragma unroll 8
    for (int ci = 0; ci < CIN; ++ci) {
        float s = sv[ci];
        acc = fmaf(wq[ci], s * s, acc);
    }
    g_decoef[t] = rsqrtf(acc + EPS);
}

// g_wmod[b][ci][kh][co][kw] = weight[co][ci][kh][kw] * s[b,ci] * decoef[b,co]
__global__ void k_wmod(const float* __restrict__ weight) {
    int t = blockIdx.x * blockDim.x + threadIdx.x;
    if (t >= BATCH * CIN * 3 * COUT * 3) return;
    int kw = t % 3;
    int co = (t / 3) & 127;
    int kh = (t / (3 * 128)) % 3;
    int ci = (t / (3 * 128 * 3)) & 127;
    int b  =  t / (3 * 128 * 3 * 128);
    float w = weight[((co * CIN + ci) * 3 + kh) * 3 + kw];
    g_wmod[t] = w * g_s[b * CIN + ci] * g_decoef[b * COUT + co];
}

// ---------------------------------------------------------------------------
// Conv kernel. CTA: (b, 32 co, 16x16 px). 256 threads, 4 co x 8 px each.
// Double-buffered cp.async staging; pre-modulated weights; vector LDS.
#define CO_T   32
#define TILE   16
#define CI_T   8
#define XPITCH 24            // floats/row staged (gx in [w0-4, w0+20)), 6 x 16B
#define XROWS  18
#define NCHNK  (CIN / CI_T)  // 16

#define XCH (CI_T * XROWS * 6)   // 864 16B chunks for x per stage
#define WCH (CI_T * 3 * 24)      // 576 16B chunks for w per stage

__global__ __launch_bounds__(256, 2)
void k_conv(const float* __restrict__ x, float* __restrict__ out) {
    __shared__ __align__(16) float xs[2][CI_T * XROWS * XPITCH];  // 2 x 13.5 KB
    __shared__ __align__(16) float ws[2][CI_T * 3 * CO_T * 3];    // 2 x 9 KB

    const int tid = threadIdx.x;
    const int b  = blockIdx.z;
    const int co_base = blockIdx.y * CO_T;
    const int h0 = (blockIdx.x >> 3) * TILE;
    const int w0 = (blockIdx.x & 7) * TILE;

    const int co_grp = tid >> 5;        // 0..7 (warp-uniform)
    const int px = tid & 31;
    const int r  = px >> 1;             // output row 0..15
    const int c8 = (px & 1) * 8;        // output col segment (0 or 8)

    const float* xb0 = x + (size_t)b * CIN * HH * WW;
    const float* wb0 = g_wmod + (size_t)b * CIN * 1152 + co_base * 3;

    // staging helper: fill buffer `buf` from input-channel chunk base c0
    auto stage = [&](int buf, int c0) {
        const float* xb = xb0 + (size_t)c0 * HH * WW;
        const uint32_t xsb = smem_u32(&xs[buf][0]);
        // x: 864 chunks; chunk i -> dst byte i*16; fully valid or fully OOB
#pragma unroll
        for (int it = 0; it < 4; ++it) {
            int i = tid + it * 256;
            if (i < XCH) {
                int ci  = i / (XROWS * 6);
                int rem = i - ci * (XROWS * 6);
                int y = rem / 6;
                int j = rem - y * 6;
                int gy = h0 - 1 + y;
                int gx = w0 - 4 + 4 * j;
                const float* src = xb + ci * (HH * WW) + gy * WW + gx;
                int ok = ((unsigned)gy < HH && (unsigned)gx <= (WW - 4)) ? 16 : 0;
                cp16(xsb + i * 16, src, ok);
            }
        }
        // w: 576 chunks; (ci,kh) row = 96 consecutive floats (32 co x 3 kw)
        const float* wb = wb0 + (size_t)c0 * 1152;
        const uint32_t wsb = smem_u32(&ws[buf][0]);
#pragma unroll
        for (int it = 0; it < 3; ++it) {
            int i = tid + it * 256;
            if (i < WCH) {
                int g = i / 24;           // ci*3 + kh
                int j = i - g * 24;
                cp16(wsb + i * 16, wb + g * (COUT * 3) + j * 4, 16);
            }
        }
    };

    float acc[4][8];
#pragma unroll
    for (int i = 0; i < 4; ++i)
#pragma unroll
        for (int j = 0; j < 8; ++j) acc[i][j] = 0.f;

    stage(0, 0);
    asm volatile("cp.async.commit_group;" ::: "memory");

    for (int c = 0; c < NCHNK; ++c) {
        if (c + 1 < NCHNK) {
            stage((c + 1) & 1, (c + 1) * CI_T);
            asm volatile("cp.async.commit_group;" ::: "memory");
            asm volatile("cp.async.wait_group 1;" ::: "memory");
        } else {
            asm volatile("cp.async.wait_group 0;" ::: "memory");
        }
        __syncthreads();

        const int buf = c & 1;
        const float* xsl = &xs[buf][0];
        const float* wsl = &ws[buf][0];
#pragma unroll 2
        for (int ci = 0; ci < CI_T; ++ci) {
#pragma unroll
            for (int kh = 0; kh < 3; ++kh) {
                // x: 16 floats via 4x LDS.128 (aligned), window used: [3..12]
                const float4* xrow = reinterpret_cast<const float4*>(
                    xsl + ci * (XROWS * XPITCH) + (r + kh) * XPITCH + c8);
                float4 a0 = xrow[0], a1 = xrow[1], a2 = xrow[2], a3 = xrow[3];
                float xr[16] = {a0.x, a0.y, a0.z, a0.w, a1.x, a1.y, a1.z, a1.w,
                                a2.x, a2.y, a2.z, a2.w, a3.x, a3.y, a3.z, a3.w};
                // w: 12 contiguous floats via 3x LDS.128 (warp-uniform broadcast)
                const float4* wp = reinterpret_cast<const float4*>(
                    wsl + (ci * 3 + kh) * (CO_T * 3) + co_grp * 12);
                float4 wA = wp[0], wB = wp[1], wC = wp[2];
                float wv[12] = {wA.x, wA.y, wA.z, wA.w, wB.x, wB.y,
                                wB.z, wB.w, wC.x, wC.y, wC.z, wC.w};
#pragma unroll
                for (int c4 = 0; c4 < 4; ++c4)
#pragma unroll
                    for (int kw = 0; kw < 3; ++kw)
#pragma unroll
                        for (int j = 0; j < 8; ++j)
                            acc[c4][j] = fmaf(wv[c4 * 3 + kw], xr[3 + j + kw],
                                              acc[c4][j]);
            }
        }
        __syncthreads();
    }

    // store (demod already folded into weights)
#pragma unroll
    for (int c4 = 0; c4 < 4; ++c4) {
        int co = co_base + co_grp * 4 + c4;
        float4* op = reinterpret_cast<float4*>(
            out + (((size_t)b * COUT + co) * HH + (h0 + r)) * WW + w0 + c8);
        op[0] = make_float4(acc[c4][0], acc[c4][1], acc[c4][2], acc[c4][3]);
        op[1] = make_float4(acc[c4][4], acc[c4][5], acc[c4][6], acc[c4][7]);
    }
}

// ---------------------------------------------------------------------------
extern "C" void kernel_launch(void* const* d_in, const int* in_sizes, int n_in,
                              void* d_out, int out_size) {
    const float* x      = (const float*)d_in[0];
    const float* style  = (const float*)d_in[1];
    const float* weight = (const float*)d_in[2];
    const float* mod_w  = (const float*)d_in[3];
    const float* mod_b  = (const float*)d_in[4];
    float* out = (float*)d_out;

    k_modscale<<<(BATCH * CIN + 255) / 256, 256>>>(style, mod_w, mod_b);
    k_wsq<<<(COUT * CIN + 255) / 256, 256>>>(weight);
    k_decoef<<<(BATCH * COUT + 255) / 256, 256>>>();
    k_wmod<<<(BATCH * CIN * 3 * COUT * 3 + 255) / 256, 256>>>(weight);

    dim3 grid((HH / TILE) * (WW / TILE), COUT / CO_T, BATCH);
    k_conv<<<grid, 256>>>(x, out);
}

// round 12
// speedup vs baseline: 4.0604x; 3.5131x over previous
#include <cuda_runtime.h>
#include <cuda_bf16.h>
#include <cstdint>

// Problem constants (fixed by reference setup_inputs)
#define BATCH 16
#define CIN   128
#define COUT  128
#define HH    128
#define WW    128
#define SS    512
#define EPS   1e-8f
#define HW    (HH * WW)

#define NCHUNKS 36                 // 9 (kh,kw) x 4 ci-blocks of 32
#define A_BYTES 16384              // 128co x 32k x 4B (fragment-major)
#define B_BYTES 16384              // 32k x 128px x 4B (fragment-major)
#define B_OFF   (2 * A_BYTES)      // B buffers after 2 A stages
#define SMEM_TOTAL (2 * (A_BYTES + B_BYTES))   // 64 KB

// Scratch (allocation-free)
__device__ float g_s[BATCH * CIN];
__device__ float g_wsq[COUT * CIN];
__device__ float g_decoef[BATCH * COUT];
// modulated tf32 weights, MMA-fragment-major:
// [b][khkw(9)][cic(4)] chunks of [k8(4)][mfrag(8)][lane(32)][e(4)]
__device__ __align__(16) float g_wmod[BATCH * 9 * 4 * 4096];   // 9.44 MB

// ---------------------------------------------------------------------------
__device__ __forceinline__ uint32_t smem_u32(const void* p) {
    return (uint32_t)__cvta_generic_to_shared(p);
}
__device__ __forceinline__ void cp16(uint32_t dst, const void* src) {
    asm volatile("cp.async.cg.shared.global [%0], [%1], 16;"
                 :: "r"(dst), "l"(src) : "memory");
}
__device__ __forceinline__ uint32_t f2tf32(float v) {
    uint32_t r; asm("cvt.rna.tf32.f32 %0, %1;" : "=r"(r) : "f"(v)); return r;
}
__device__ __forceinline__ void mma8(float* d, const uint32_t* a, const uint32_t* b) {
    asm volatile(
        "mma.sync.aligned.m16n8k8.row.col.f32.tf32.tf32.f32 "
        "{%0,%1,%2,%3}, {%4,%5,%6,%7}, {%8,%9}, {%0,%1,%2,%3};"
        : "+f"(d[0]), "+f"(d[1]), "+f"(d[2]), "+f"(d[3])
        : "r"(a[0]), "r"(a[1]), "r"(a[2]), "r"(a[3]), "r"(b[0]), "r"(b[1]));
}

// ---------------------------------------------------------------------------
__global__ void k_modscale(const float* __restrict__ style,
                           const float* __restrict__ mod_w,
                           const float* __restrict__ mod_b) {
    int t = blockIdx.x * blockDim.x + threadIdx.x;
    if (t >= BATCH * CIN) return;
    int b = t >> 7, ci = t & 127;
    const float* st = style + b * SS;
    const float* mw = mod_w + ci * SS;
    float acc = 0.f;
#pragma unroll 8
    for (int j = 0; j < SS; ++j) acc = fmaf(st[j], mw[j], acc);
    g_s[t] = acc + mod_b[ci];
}

__global__ void k_wsq(const float* __restrict__ weight) {
    int t = blockIdx.x * blockDim.x + threadIdx.x;
    if (t >= COUT * CIN) return;
    const float* w = weight + t * 9;
    float acc = 0.f;
#pragma unroll
    for (int k = 0; k < 9; ++k) acc = fmaf(w[k], w[k], acc);
    g_wsq[t] = acc;
}

__global__ void k_decoef() {
    int t = blockIdx.x * blockDim.x + threadIdx.x;
    if (t >= BATCH * COUT) return;
    int b = t >> 7, co = t & 127;
    const float* sv = g_s + b * CIN;
    const float* wq = g_wsq + co * CIN;
    float acc = 0.f;
#pragma unroll 8
    for (int ci = 0; ci < CIN; ++ci) {
        float s = sv[ci];
        acc = fmaf(wq[ci], s * s, acc);
    }
    g_decoef[t] = rsqrtf(acc + EPS);
}

// Fragment-major modulated weights.
// For m16n8k8 tf32 A-fragment: lane l -> r=l>>2, c=l&3;
// e0=A[r][c], e1=A[r+8][c], e2=A[r][c+4], e3=A[r+8][c+4].
__global__ void k_wmod(const float* __restrict__ weight) {
    int t = blockIdx.x * blockDim.x + threadIdx.x;
    if (t >= BATCH * 9 * 4 * 4096) return;
    int e    = t & 3;
    int lane = (t >> 2) & 31;
    int mf   = (t >> 7) & 7;
    int k8   = (t >> 10) & 3;
    int cic  = (t >> 12) & 3;
    int rest = t >> 14;
    int khkw = rest % 9;
    int b    = rest / 9;
    int r = lane >> 2, c = lane & 3;
    int co = mf * 16 + r + ((e & 1) ? 8 : 0);
    int ci = cic * 32 + k8 * 8 + c + ((e & 2) ? 4 : 0);
    int kh = khkw / 3, kw = khkw % 3;
    float w = weight[((co * CIN + ci) * 3 + kh) * 3 + kw];
    float v = w * g_s[b * CIN + ci] * g_decoef[b * COUT + co];
    g_wmod[t] = __uint_as_float(f2tf32(v));
}

// ---------------------------------------------------------------------------
// TF32 mma.sync implicit-GEMM conv.
// CTA: (b, 128 co, 1 image row = 128 px). 256 threads = 8 warps (2m x 4n).
// Warp tile 64co x 32px; acc = 4x4 fragments x 4 fp32.
__global__ __launch_bounds__(256, 2)
void k_conv(const float* __restrict__ x, float* __restrict__ out) {
    extern __shared__ __align__(16) char smem_raw[];
    const uint32_t base = smem_u32(smem_raw);

    const int tid = threadIdx.x;
    const int wid = tid >> 5;
    const int lane = tid & 31;
    const int b  = blockIdx.y;
    const int y0 = blockIdx.x;
    const int mw = wid >> 2;            // 0..1
    const int nw = wid & 3;             // 0..3

    // B staging ids
    const int px = tid & 127;
    const int hB = tid >> 7;            // 0..1 (which half of 32 k-rows)
    const int nfrag_s = px >> 3;
    const int nn = px & 7;
    const int f3 = nfrag_s & 3;

    float acc[4][4][4];
#pragma unroll
    for (int i = 0; i < 4; ++i)
#pragma unroll
        for (int j = 0; j < 4; ++j)
#pragma unroll
            for (int q = 0; q < 4; ++q) acc[i][j][q] = 0.f;

    float vb[16];

    auto stageA = [&](int c) {
        const int s = c & 1;
        const float* asrc = g_wmod + ((size_t)b * 36 + c) * 4096;
        const uint32_t abase = base + s * A_BYTES;
#pragma unroll
        for (int it = 0; it < 4; ++it) {
            int i = tid + it * 256;
            cp16(abase + i * 16, asrc + i * 4);
        }
        asm volatile("cp.async.commit_group;" ::: "memory");
    };
    auto ldgB = [&](int c) {
        const int khkw = c >> 2, cic = c & 3;
        const int kh = khkw / 3, kw = khkw - kh * 3;
        const int gy = y0 + kh - 1;
        const int gx = px + kw - 1;
        const bool ok = ((unsigned)gy < HH) & ((unsigned)gx < WW);
        const float* p = x + (((size_t)b * CIN + cic * 32 + hB * 16) * HH + gy) * WW + gx;
#pragma unroll
        for (int j = 0; j < 8; ++j) {
            int cio = (j >> 2) * 8 + (j & 3);
            vb[2 * j]     = ok ? __ldg(p + cio * HW)       : 0.f;
            vb[2 * j + 1] = ok ? __ldg(p + (cio + 4) * HW) : 0.f;
        }
    };
    auto stsB = [&](int c) {
        const int s = c & 1;
        const uint32_t bbase = base + B_OFF + s * B_BYTES;
#pragma unroll
        for (int j = 0; j < 8; ++j) {
            int k8 = 2 * hB + (j >> 2);
            int m = j & 3;
            uint32_t slot = (uint32_t)((nn << 2) | (m ^ f3));
            uint32_t addr = bbase + (((uint32_t)(k8 * 16 + nfrag_s) * 32 + slot) << 3);
            uint32_t r0 = f2tf32(vb[2 * j]);
            uint32_t r1 = f2tf32(vb[2 * j + 1]);
            asm volatile("st.shared.v2.b32 [%0], {%1,%2};"
                         :: "r"(addr), "r"(r0), "r"(r1) : "memory");
        }
    };

    // prologue: stage chunk 0 (A async, B sync)
    stageA(0);
    ldgB(0);
    stsB(0);
    asm volatile("cp.async.wait_group 0;" ::: "memory");
    __syncthreads();

    for (int c = 0; c < NCHUNKS; ++c) {
        if (c + 1 < NCHUNKS) {
            stageA(c + 1);
            ldgB(c + 1);
        }
        // ---- MMA over chunk c ----
        const int s = c & 1;
        const uint32_t abase = base + s * A_BYTES;
        const uint32_t bbase = base + B_OFF + s * B_BYTES;
#pragma unroll
        for (int k8 = 0; k8 < 4; ++k8) {
            uint32_t av[4][4];
#pragma unroll
            for (int ai = 0; ai < 4; ++ai) {
                uint32_t addr = abase +
                    (((uint32_t)(k8 * 8 + mw * 4 + ai) * 32 + lane) << 4);
                asm volatile("ld.shared.v4.b32 {%0,%1,%2,%3}, [%4];"
                             : "=r"(av[ai][0]), "=r"(av[ai][1]),
                               "=r"(av[ai][2]), "=r"(av[ai][3])
                             : "r"(addr));
            }
            uint32_t bv[4][2];
#pragma unroll
            for (int fi = 0; fi < 4; ++fi) {
                int nf = nw * 4 + fi;
                uint32_t addr = bbase +
                    (((uint32_t)(k8 * 16 + nf) * 32 + (uint32_t)(lane ^ fi)) << 3);
                asm volatile("ld.shared.v2.b32 {%0,%1}, [%2];"
                             : "=r"(bv[fi][0]), "=r"(bv[fi][1]) : "r"(addr));
            }
#pragma unroll
            for (int ai = 0; ai < 4; ++ai)
#pragma unroll
                for (int fi = 0; fi < 4; ++fi)
                    mma8(acc[ai][fi], av[ai], bv[fi]);
        }
        if (c + 1 < NCHUNKS) {
            stsB(c + 1);
            asm volatile("cp.async.wait_group 0;" ::: "memory");
        }
        __syncthreads();
    }

    // ---- epilogue ----
    const int r = lane >> 2, q = lane & 3;
#pragma unroll
    for (int ai = 0; ai < 4; ++ai) {
        int co0 = mw * 64 + ai * 16 + r;
#pragma unroll
        for (int fi = 0; fi < 4; ++fi) {
            int pxo = nw * 32 + fi * 8 + 2 * q;
            float* o0 = out + (((size_t)b * COUT + co0) * HH + y0) * WW + pxo;
            float* o1 = o0 + 8 * (size_t)HW;       // co0 + 8
            reinterpret_cast<float2*>(o0)[0] =
                make_float2(acc[ai][fi][0], acc[ai][fi][1]);
            reinterpret_cast<float2*>(o1)[0] =
                make_float2(acc[ai][fi][2], acc[ai][fi][3]);
        }
    }
}

// ---------------------------------------------------------------------------
extern "C" void kernel_launch(void* const* d_in, const int* in_sizes, int n_in,
                              void* d_out, int out_size) {
    const float* x      = (const float*)d_in[0];
    const float* style  = (const float*)d_in[1];
    const float* weight = (const float*)d_in[2];
    const float* mod_w  = (const float*)d_in[3];
    const float* mod_b  = (const float*)d_in[4];
    float* out = (float*)d_out;

    k_modscale<<<(BATCH * CIN + 255) / 256, 256>>>(style, mod_w, mod_b);
    k_wsq<<<(COUT * CIN + 255) / 256, 256>>>(weight);
    k_decoef<<<(BATCH * COUT + 255) / 256, 256>>>();
    k_wmod<<<(BATCH * 9 * 4 * 4096 + 255) / 256, 256>>>(weight);

    cudaFuncSetAttribute(k_conv, cudaFuncAttributeMaxDynamicSharedMemorySize,
                         SMEM_TOTAL);
    dim3 grid(HH, BATCH);
    k_conv<<<grid, 256, SMEM_TOTAL>>>(x, out);
}

// round 13
// speedup vs baseline: 5.9804x; 1.4728x over previous
#include <cuda_runtime.h>
#include <cuda_fp16.h>
#include <cstdint>

// Problem constants (fixed by reference setup_inputs)
#define BATCH 16
#define CIN   128
#define COUT  128
#define HH    128
#define WW    128
#define SS    512
#define EPS   1e-8f
#define HW    (HH * WW)

#define NCHUNKS 36                 // 9 (kh,kw) x 4 ci-blocks of 32
#define A_BYTES 8192               // 128co x 32k fp16, fragment-major
#define B_FRAG_STRIDE 272          // 32 lanes x 8B + 16B pad
#define B_BYTES (32 * B_FRAG_STRIDE)   // 8704
#define B_OFF   (2 * A_BYTES)
#define SMEM_TOTAL (2 * A_BYTES + 2 * B_BYTES)   // 33792

// Scratch (allocation-free)
__device__ float g_s[BATCH * CIN];
__device__ float g_wsq[COUT * CIN];
__device__ float g_decoef[BATCH * COUT];
// modulated fp16x2 weights, m16n8k16-fragment-major:
// [b][khkw(9)][cic(4)] x [k16(2)][mfrag(8)][lane(32)][reg(4)] u32
__device__ __align__(16) uint32_t g_wmod[BATCH * 9 * 4 * 2048];  // 4.7 MB

// ---------------------------------------------------------------------------
__device__ __forceinline__ uint32_t smem_u32(const void* p) {
    return (uint32_t)__cvta_generic_to_shared(p);
}
__device__ __forceinline__ void cp16(uint32_t dst, const void* src) {
    asm volatile("cp.async.cg.shared.global [%0], [%1], 16;"
                 :: "r"(dst), "l"(src) : "memory");
}
__device__ __forceinline__ uint32_t packh2(float lo, float hi) {
    __half2 h = __floats2half2_rn(lo, hi);
    return *reinterpret_cast<uint32_t*>(&h);
}
__device__ __forceinline__ void mma16(float* d, const uint32_t* a, const uint32_t* b) {
    asm volatile(
        "mma.sync.aligned.m16n8k16.row.col.f32.f16.f16.f32 "
        "{%0,%1,%2,%3}, {%4,%5,%6,%7}, {%8,%9}, {%0,%1,%2,%3};"
        : "+f"(d[0]), "+f"(d[1]), "+f"(d[2]), "+f"(d[3])
        : "r"(a[0]), "r"(a[1]), "r"(a[2]), "r"(a[3]), "r"(b[0]), "r"(b[1]));
}

// ---------------------------------------------------------------------------
__global__ void k_modscale(const float* __restrict__ style,
                           const float* __restrict__ mod_w,
                           const float* __restrict__ mod_b) {
    int t = blockIdx.x * blockDim.x + threadIdx.x;
    if (t >= BATCH * CIN) return;
    int b = t >> 7, ci = t & 127;
    const float* st = style + b * SS;
    const float* mw = mod_w + ci * SS;
    float acc = 0.f;
#pragma unroll 8
    for (int j = 0; j < SS; ++j) acc = fmaf(st[j], mw[j], acc);
    g_s[t] = acc + mod_b[ci];
}

__global__ void k_wsq(const float* __restrict__ weight) {
    int t = blockIdx.x * blockDim.x + threadIdx.x;
    if (t >= COUT * CIN) return;
    const float* w = weight + t * 9;
    float acc = 0.f;
#pragma unroll
    for (int k = 0; k < 9; ++k) acc = fmaf(w[k], w[k], acc);
    g_wsq[t] = acc;
}

__global__ void k_decoef() {
    int t = blockIdx.x * blockDim.x + threadIdx.x;
    if (t >= BATCH * COUT) return;
    int b = t >> 7, co = t & 127;
    const float* sv = g_s + b * CIN;
    const float* wq = g_wsq + co * CIN;
    float acc = 0.f;
#pragma unroll 8
    for (int ci = 0; ci < CIN; ++ci) {
        float s = sv[ci];
        acc = fmaf(wq[ci], s * s, acc);
    }
    g_decoef[t] = rsqrtf(acc + EPS);
}

// A fragment (m16n8k16 f16, row-major A): lane l -> r=l>>2, c=l&3.
// reg e0: A[r][2c..2c+1], e1: A[r+8][2c..], e2: A[r][2c+8..], e3: A[r+8][2c+8..]
__global__ void k_wmod(const float* __restrict__ weight) {
    int t = blockIdx.x * blockDim.x + threadIdx.x;
    if (t >= BATCH * 9 * 4 * 2048) return;
    int e    = t & 3;
    int lane = (t >> 2) & 31;
    int mf   = (t >> 7) & 7;
    int k16  = (t >> 10) & 1;
    int cic  = (t >> 11) & 3;
    int rest = t >> 13;
    int khkw = rest % 9;
    int b    = rest / 9;
    int r = lane >> 2, c = lane & 3;
    int co  = mf * 16 + r + (e & 1) * 8;
    int ci0 = cic * 32 + k16 * 16 + 2 * c + ((e >> 1) & 1) * 8;
    int kh = khkw / 3, kw = khkw % 3;
    float dc = g_decoef[b * COUT + co];
    float v0 = weight[((co * CIN + ci0) * 3 + kh) * 3 + kw]
               * g_s[b * CIN + ci0] * dc;
    float v1 = weight[((co * CIN + ci0 + 1) * 3 + kh) * 3 + kw]
               * g_s[b * CIN + ci0 + 1] * dc;
    g_wmod[t] = packh2(v0, v1);
}

// ---------------------------------------------------------------------------
// FP16 mma.sync implicit-GEMM conv.
// CTA: (b, 128 co, 1 image row = 128 px). 256 threads = 8 warps (2m x 4n).
// Warp tile 64co x 32px; acc = 4x4 fragments x 4 fp32.
__global__ __launch_bounds__(256, 2)
void k_conv(const float* __restrict__ x, float* __restrict__ out) {
    extern __shared__ __align__(16) char smem_raw[];
    const uint32_t base = smem_u32(smem_raw);

    const int tid = threadIdx.x;
    const int wid = tid >> 5;
    const int lane = tid & 31;
    const int b  = blockIdx.y;
    const int y0 = blockIdx.x;
    const int mw = wid >> 2;            // 0..1
    const int nw = wid & 3;             // 0..3

    // B staging ids: thread = (px, hB); hB selects k16 block (ci 0-15 / 16-31)
    const int px = tid & 127;
    const int hB = tid >> 7;
    const int nf_s = px >> 3;
    const int laneb = (px & 7) * 4;

    float acc[4][4][4];
#pragma unroll
    for (int i = 0; i < 4; ++i)
#pragma unroll
        for (int j = 0; j < 4; ++j)
#pragma unroll
            for (int q = 0; q < 4; ++q) acc[i][j][q] = 0.f;

    float vb[16];

    auto stageA = [&](int c) {
        const int s = c & 1;
        const uint32_t* asrc = g_wmod + ((size_t)b * 36 + c) * 2048;
        const uint32_t abase = base + s * A_BYTES;
#pragma unroll
        for (int it = 0; it < 2; ++it) {
            int i = tid + it * 256;        // 0..511, 16B each
            cp16(abase + i * 16, asrc + i * 4);
        }
        asm volatile("cp.async.commit_group;" ::: "memory");
    };
    auto ldgB = [&](int c) {
        const int khkw = c >> 2, cic = c & 3;
        const int kh = khkw / 3, kw = khkw - kh * 3;
        const int gy = y0 + kh - 1;
        const int gx = px + kw - 1;
        const bool ok = ((unsigned)gy < HH) & ((unsigned)gx < WW);
        const float* p = x + (((size_t)b * CIN + cic * 32 + hB * 16) * HH + gy) * WW + gx;
#pragma unroll
        for (int j = 0; j < 16; ++j)
            vb[j] = ok ? __ldg(p + j * HW) : 0.f;
    };
    auto stsB = [&](int c) {
        const int s = c & 1;
        const uint32_t bbase = base + B_OFF + s * B_BYTES;
        const int fb = hB * 16 + nf_s;
#pragma unroll
        for (int q = 0; q < 4; ++q) {
            uint32_t b0 = packh2(vb[2 * q], vb[2 * q + 1]);
            uint32_t b1 = packh2(vb[2 * q + 8], vb[2 * q + 9]);
            uint32_t addr = bbase + fb * B_FRAG_STRIDE + (laneb + q) * 8;
            asm volatile("st.shared.v2.b32 [%0], {%1,%2};"
                         :: "r"(addr), "r"(b0), "r"(b1) : "memory");
        }
    };

    // prologue
    stageA(0);
    ldgB(0);
    stsB(0);
    asm volatile("cp.async.wait_group 0;" ::: "memory");
    __syncthreads();

    for (int c = 0; c < NCHUNKS; ++c) {
        if (c + 1 < NCHUNKS) {
            stageA(c + 1);
            ldgB(c + 1);
        }
        // ---- MMA over chunk c (K=32 -> 2 k16 steps) ----
        const int s = c & 1;
        const uint32_t abase = base + s * A_BYTES;
        const uint32_t bbase = base + B_OFF + s * B_BYTES;
#pragma unroll
        for (int k16 = 0; k16 < 2; ++k16) {
            uint32_t av[4][4];
#pragma unroll
            for (int ai = 0; ai < 4; ++ai) {
                uint32_t addr = abase +
                    (((uint32_t)(k16 * 8 + mw * 4 + ai) * 32 + lane) << 4);
                asm volatile("ld.shared.v4.b32 {%0,%1,%2,%3}, [%4];"
                             : "=r"(av[ai][0]), "=r"(av[ai][1]),
                               "=r"(av[ai][2]), "=r"(av[ai][3])
                             : "r"(addr));
            }
            uint32_t bv[4][2];
#pragma unroll
            for (int fi = 0; fi < 4; ++fi) {
                int fb = k16 * 16 + nw * 4 + fi;
                uint32_t addr = bbase + fb * B_FRAG_STRIDE + lane * 8;
                asm volatile("ld.shared.v2.b32 {%0,%1}, [%2];"
                             : "=r"(bv[fi][0]), "=r"(bv[fi][1]) : "r"(addr));
            }
#pragma unroll
            for (int ai = 0; ai < 4; ++ai)
#pragma unroll
                for (int fi = 0; fi < 4; ++fi)
                    mma16(acc[ai][fi], av[ai], bv[fi]);
        }
        if (c + 1 < NCHUNKS) {
            stsB(c + 1);
            asm volatile("cp.async.wait_group 0;" ::: "memory");
        }
        __syncthreads();
    }

    // ---- epilogue: D fragment row r = lane>>2, cols 2q (q=lane&3) ----
    const int r = lane >> 2, q = lane & 3;
#pragma unroll
    for (int ai = 0; ai < 4; ++ai) {
        int co0 = mw * 64 + ai * 16 + r;
#pragma unroll
        for (int fi = 0; fi < 4; ++fi) {
            int pxo = nw * 32 + fi * 8 + 2 * q;
            float* o0 = out + (((size_t)b * COUT + co0) * HH + y0) * WW + pxo;
            float* o1 = o0 + 8 * (size_t)HW;       // co0 + 8
            reinterpret_cast<float2*>(o0)[0] =
                make_float2(acc[ai][fi][0], acc[ai][fi][1]);
            reinterpret_cast<float2*>(o1)[0] =
                make_float2(acc[ai][fi][2], acc[ai][fi][3]);
        }
    }
}

// ---------------------------------------------------------------------------
extern "C" void kernel_launch(void* const* d_in, const int* in_sizes, int n_in,
                              void* d_out, int out_size) {
    const float* x      = (const float*)d_in[0];
    const float* style  = (const float*)d_in[1];
    const float* weight = (const float*)d_in[2];
    const float* mod_w  = (const float*)d_in[3];
    const float* mod_b  = (const float*)d_in[4];
    float* out = (float*)d_out;

    k_modscale<<<(BATCH * CIN + 255) / 256, 256>>>(style, mod_w, mod_b);
    k_wsq<<<(COUT * CIN + 255) / 256, 256>>>(weight);
    k_decoef<<<(BATCH * COUT + 255) / 256, 256>>>();
    k_wmod<<<(BATCH * 9 * 4 * 2048 + 255) / 256, 256>>>(weight);

    cudaFuncSetAttribute(k_conv, cudaFuncAttributeMaxDynamicSharedMemorySize,
                         SMEM_TOTAL);
    dim3 grid(HH, BATCH);
    k_conv<<<grid, 256, SMEM_TOTAL>>>(x, out);
}